// round 12
// baseline (speedup 1.0000x reference)
#include <cuda_runtime.h>
#include <cstdint>

#define TABLE_SIZE 524288u          // 2^19 -> modulo is a mask
#define NUM_LEVELS 16
#define N_POINTS (1u << 20)
#define HASH_PRIME 2654435761u

#define BINS_PER_AXIS 256u
#define NBINS (BINS_PER_AXIS * BINS_PER_AXIS)   // 65536 spatial bins

// -------- allocation-free scratch (device globals, zero-init at load) --------
__device__ uint32_t g_hist[NBINS];       // always zero OUTSIDE a launch chain:
                                         // hist fills it, scanA reads+rezeroes.
__device__ uint32_t g_cursor[NBINS];     // exclusive within row after scanA
__device__ uint32_t g_rowsum[BINS_PER_AXIS];
__device__ uint32_t g_rowoff[BINS_PER_AXIS];
__device__ uint32_t g_rank[N_POINTS];    // within-bin rank from hist pass
__device__ uint32_t g_inv[N_POINTS];     // inverse permutation: sorted pos -> p

// scalings: floor(16 * (2^0.4)^l) in fp32, matching the reference exactly.
__constant__ float kScale[NUM_LEVELS] = {
    16.0f, 21.0f, 27.0f, 36.0f, 48.0f, 64.0f, 84.0f, 111.0f,
    147.0f, 194.0f, 256.0f, 337.0f, 445.0f, 588.0f, 776.0f, 1024.0f
};

__device__ __forceinline__ uint32_t bin_key(float xv, float yv)
{
    uint32_t kx = (uint32_t)(xv * 256.0f);
    uint32_t ky = (uint32_t)(yv * 256.0f);
    kx = kx > 255u ? 255u : kx;
    ky = ky > 255u ? 255u : ky;
    return (ky << 8) | kx;               // row-major; bin>>8 = ky
}

// ---------------- sort pipeline ----------------
// histogram + per-point within-bin rank (the atomic's return value)
__global__ void hist_kernel(const float2* __restrict__ x)
{
    const uint32_t p = blockIdx.x * 256u + threadIdx.x;
    const float2 xp = __ldg(&x[p]);
    g_rank[p] = atomicAdd(&g_hist[bin_key(xp.x, xp.y)], 1u);
}

// scanA: 256 blocks; block b scans bins [b*256, b*256+256) -> local exclusive.
// Also re-zeroes g_hist so the next graph replay starts clean (no zero kernel).
__global__ void scanA_kernel()
{
    __shared__ uint32_t s[256];
    const uint32_t t = threadIdx.x;
    const uint32_t i = blockIdx.x * 256u + t;
    const uint32_t v = g_hist[i];
    g_hist[i] = 0u;                             // restore for next replay
    s[t] = v;
    __syncthreads();
    #pragma unroll
    for (uint32_t off = 1u; off < 256u; off <<= 1) {
        uint32_t u = (t >= off) ? s[t - off] : 0u;
        __syncthreads();
        s[t] += u;
        __syncthreads();
    }
    g_cursor[i] = s[t] - v;                     // exclusive within row
    if (t == 255u) g_rowsum[blockIdx.x] = s[t]; // row total
}

// scanB: one tiny block scans the 256 row sums -> row offsets
__global__ void scanB_kernel()
{
    __shared__ uint32_t s[256];
    const uint32_t t = threadIdx.x;
    const uint32_t v = g_rowsum[t];
    s[t] = v;
    __syncthreads();
    #pragma unroll
    for (uint32_t off = 1u; off < 256u; off <<= 1) {
        uint32_t u = (t >= off) ? s[t - off] : 0u;
        __syncthreads();
        s[t] += u;
        __syncthreads();
    }
    g_rowoff[t] = s[t] - v;
}

// scatter: ATOMIC-FREE, sync-free, 4B payload. g_inv[pos] = p.
__global__ void scatter_kernel(const float2* __restrict__ x)
{
    const uint32_t p = blockIdx.x * 256u + threadIdx.x;
    const float2 xp = __ldg(&x[p]);              // coalesced
    const uint32_t rk = g_rank[p];               // coalesced
    const uint32_t bin = bin_key(xp.x, xp.y);
    const uint32_t pos = __ldg(&g_cursor[bin]) + __ldg(&g_rowoff[bin >> 8]) + rk;
    g_inv[pos] = p;                              // scattered 4B store
}

// ---------------- main encode kernel ----------------
// lane = sorted point; warp = 32 spatially-adjacent points; loop over levels.
// Transpose through smem with 9-float2 stride: bank-pair = (9q+p) mod 16 ->
// exactly 2-way (the 2-phase floor) on both STS.64 and LDS.64.
#define M_BLOCK 256
#define ROW_F2 9                     // float2 stride per point per half

__global__ __launch_bounds__(M_BLOCK)
void hash_encode_kernel(const uint32_t* __restrict__ inv,
                        const float2* __restrict__ x,
                        const float2* __restrict__ table,
                        float2* __restrict__ out)
{
    __shared__ float2 s_buf[M_BLOCK / 32][32 * ROW_F2];

    const uint32_t tid  = threadIdx.x;
    const uint32_t lane = tid & 31u;
    float2* const srow  = s_buf[tid >> 5];

    const uint32_t pos = blockIdx.x * M_BLOCK + tid;  // sorted position
    const uint32_t og  = __ldg(&inv[pos]);            // coalesced 4B
    const float2   pt  = __ldg(&x[og]);               // one divergent gather

    const uint32_t pc = lane >> 3;       // 0..3 point-group for store passes
    const uint32_t pp = lane & 7u;       // piece 0..7

    #pragma unroll
    for (uint32_t half = 0; half < 2u; ++half) {
        #pragma unroll
        for (uint32_t h = 0; h < 8u; ++h) {
            const uint32_t l = half * 8u + h;
            const float s  = kScale[l];
            const float sx = pt.x * s;
            const float sy = pt.y * s;

            const float fxf = floorf(sx);
            const float fyf = floorf(sy);
            const uint32_t fx = (uint32_t)(int32_t)fxf;
            const uint32_t fy = (uint32_t)(int32_t)fyf;
            const uint32_t cx = (uint32_t)(int32_t)ceilf(sx);
            const uint32_t cy = (uint32_t)(int32_t)ceilf(sy);
            const float ox = sx - fxf;
            const float oy = sy - fyf;

            const uint32_t base = l * TABLE_SIZE;
            const uint32_t hyc  = cy * HASH_PRIME;
            const uint32_t hyf  = fy * HASH_PRIME;
            // v0=(cx,cy) v1=(cx,fy) v2=(fx,cy) v3=(fx,fy)
            const uint32_t h0 = ((cx ^ hyc) & (TABLE_SIZE - 1u)) + base;
            const uint32_t h1 = ((cx ^ hyf) & (TABLE_SIZE - 1u)) + base;
            const uint32_t h2 = ((fx ^ hyc) & (TABLE_SIZE - 1u)) + base;
            const uint32_t h3 = ((fx ^ hyf) & (TABLE_SIZE - 1u)) + base;

            const float2 f0 = __ldg(&table[h0]);
            const float2 f1 = __ldg(&table[h1]);
            const float2 f2 = __ldg(&table[h2]);
            const float2 f3 = __ldg(&table[h3]);

            const float omx = 1.0f - ox;
            const float omy = 1.0f - oy;
            float2 e;
            e.x = (f0.x * ox + f3.x * omx) * oy + (f1.x * ox + f2.x * omx) * omy;
            e.y = (f0.y * ox + f3.y * omx) * oy + (f1.y * ox + f2.y * omx) * omy;

            srow[lane * ROW_F2 + h] = e;      // STS.64, 2-way max
        }
        __syncwarp();

        // transpose out: pass covers points {pc*8, .., pc*8+7}
        #pragma unroll
        for (uint32_t pass = 0; pass < 8u; ++pass) {
            const uint32_t q = pc * 8u + pass;               // warp point
            const float2 v = srow[q * ROW_F2 + pp];          // LDS.64, 2-way max
            const uint32_t oq = __shfl_sync(0xffffffffu, og, (int)q);
            out[(size_t)oq * 16u + half * 8u + pp] = v;      // STG.64, 4 rows/instr
        }
        __syncwarp();
    }
}

extern "C" void kernel_launch(void* const* d_in, const int* in_sizes, int n_in,
                              void* d_out, int out_size)
{
    const float2* x     = (const float2*)d_in[0];   // (N_POINTS, 2) float32
    const float2* table = (const float2*)d_in[1];   // (TABLE_SIZE*16, 2) float32
    float2* out = (float2*)d_out;                   // (N_POINTS, 32) float32

    uint32_t* inv;
    cudaGetSymbolAddress((void**)&inv, g_inv);

    hist_kernel     <<<N_POINTS / 256, 256>>>(x);
    scanA_kernel    <<<256, 256>>>();
    scanB_kernel    <<<1, 256>>>();
    scatter_kernel  <<<N_POINTS / 256, 256>>>(x);
    hash_encode_kernel<<<N_POINTS / M_BLOCK, M_BLOCK>>>(inv, x, table, out);
}

// round 13
// speedup vs baseline: 1.0195x; 1.0195x over previous
#include <cuda_runtime.h>
#include <cstdint>

#define TABLE_SIZE 524288u          // 2^19 -> modulo is a mask
#define NUM_LEVELS 16
#define N_POINTS (1u << 20)
#define HASH_PRIME 2654435761u

#define BINS_PER_AXIS 256u
#define NBINS (BINS_PER_AXIS * BINS_PER_AXIS)   // 65536 spatial bins

// -------- allocation-free scratch (device globals, zero-init at load) --------
__device__ uint32_t g_hist[NBINS];       // zero outside a launch chain:
                                         // hist fills it, scanA reads+rezeroes.
__device__ uint32_t g_cursor[NBINS];     // after scanB_add: global bin offset
__device__ uint32_t g_rowsum[BINS_PER_AXIS];
__device__ uint32_t g_rank[N_POINTS];    // within-bin rank from hist pass
__device__ uint32_t g_inv[N_POINTS];     // inverse permutation: sorted pos -> p

// scalings: floor(16 * (2^0.4)^l) in fp32, matching the reference exactly.
__constant__ float kScale[NUM_LEVELS] = {
    16.0f, 21.0f, 27.0f, 36.0f, 48.0f, 64.0f, 84.0f, 111.0f,
    147.0f, 194.0f, 256.0f, 337.0f, 445.0f, 588.0f, 776.0f, 1024.0f
};

__device__ __forceinline__ uint32_t bin_key(float xv, float yv)
{
    uint32_t kx = (uint32_t)(xv * 256.0f);
    uint32_t ky = (uint32_t)(yv * 256.0f);
    kx = kx > 255u ? 255u : kx;
    ky = ky > 255u ? 255u : ky;
    return (ky << 8) | kx;               // row-major; bin>>8 = ky
}

// ---------------- sort pipeline ----------------
// histogram + per-point within-bin rank; 2 points/thread (independent chains)
__global__ void hist_kernel(const float2* __restrict__ x)
{
    const uint32_t p0 = blockIdx.x * 512u + threadIdx.x;
    const uint32_t p1 = p0 + 256u;
    const float2 a = __ldg(&x[p0]);
    const float2 b = __ldg(&x[p1]);
    const uint32_t ba = bin_key(a.x, a.y);
    const uint32_t bb = bin_key(b.x, b.y);
    g_rank[p0] = atomicAdd(&g_hist[ba], 1u);
    g_rank[p1] = atomicAdd(&g_hist[bb], 1u);
}

// scanA: 256 blocks; block b scans bins [b*256, b*256+256) -> local exclusive.
// Also re-zeroes g_hist so the next graph replay starts clean.
__global__ void scanA_kernel()
{
    __shared__ uint32_t s[256];
    const uint32_t t = threadIdx.x;
    const uint32_t i = blockIdx.x * 256u + t;
    const uint32_t v = g_hist[i];
    g_hist[i] = 0u;                             // restore for next replay
    s[t] = v;
    __syncthreads();
    #pragma unroll
    for (uint32_t off = 1u; off < 256u; off <<= 1) {
        uint32_t u = (t >= off) ? s[t - off] : 0u;
        __syncthreads();
        s[t] += u;
        __syncthreads();
    }
    g_cursor[i] = s[t] - v;                     // exclusive within row
    if (t == 255u) g_rowsum[blockIdx.x] = s[t]; // row total
}

// scanB_add: 256 blocks. Each block redundantly scans the 256 row sums
// (cheap, parallel) and folds its row's offset straight into g_cursor,
// making the cursor a global bin offset. No serial 1-block launch.
__global__ void scanB_add_kernel()
{
    __shared__ uint32_t s[256];
    const uint32_t t = threadIdx.x;
    const uint32_t v = g_rowsum[t];
    s[t] = v;
    __syncthreads();
    #pragma unroll
    for (uint32_t off = 1u; off < 256u; off <<= 1) {
        uint32_t u = (t >= off) ? s[t - off] : 0u;
        __syncthreads();
        s[t] += u;
        __syncthreads();
    }
    const uint32_t rowoff = s[blockIdx.x] - g_rowsum[blockIdx.x];
    g_cursor[blockIdx.x * 256u + t] += rowoff;
}

// scatter: ATOMIC-FREE, sync-free, 4 points/thread (MLP=4 pure-load chains).
// pos = cursor[bin] + rank  (single gather in the chain now).
__global__ void scatter_kernel(const float2* __restrict__ x)
{
    const uint32_t p0 = blockIdx.x * 1024u + threadIdx.x;

    float2  xp[4];
    uint32_t rk[4], bin[4];
    #pragma unroll
    for (uint32_t k = 0; k < 4u; ++k)
        xp[k] = __ldg(&x[p0 + k * 256u]);
    #pragma unroll
    for (uint32_t k = 0; k < 4u; ++k)
        rk[k] = g_rank[p0 + k * 256u];
    #pragma unroll
    for (uint32_t k = 0; k < 4u; ++k)
        bin[k] = bin_key(xp[k].x, xp[k].y);
    uint32_t cur[4];
    #pragma unroll
    for (uint32_t k = 0; k < 4u; ++k)
        cur[k] = __ldg(&g_cursor[bin[k]]);
    #pragma unroll
    for (uint32_t k = 0; k < 4u; ++k)
        g_inv[cur[k] + rk[k]] = p0 + k * 256u;   // scattered 4B store
}

// ---------------- main encode kernel ----------------
// lane = sorted point; warp = 32 spatially-adjacent points; loop over levels.
// Transpose through smem with 9-float2 stride: bank-pair = (9q+p) mod 16 ->
// exactly 2-way (the 2-phase floor) on both STS.64 and LDS.64.
#define M_BLOCK 256
#define ROW_F2 9                     // float2 stride per point per half

__global__ __launch_bounds__(M_BLOCK)
void hash_encode_kernel(const uint32_t* __restrict__ inv,
                        const float2* __restrict__ x,
                        const float2* __restrict__ table,
                        float2* __restrict__ out)
{
    __shared__ float2 s_buf[M_BLOCK / 32][32 * ROW_F2];

    const uint32_t tid  = threadIdx.x;
    const uint32_t lane = tid & 31u;
    float2* const srow  = s_buf[tid >> 5];

    const uint32_t pos = blockIdx.x * M_BLOCK + tid;  // sorted position
    const uint32_t og  = __ldg(&inv[pos]);            // coalesced 4B
    const float2   pt  = __ldg(&x[og]);               // one divergent gather

    const uint32_t pc = lane >> 3;       // 0..3 point-group for store passes
    const uint32_t pp = lane & 7u;       // piece 0..7

    #pragma unroll
    for (uint32_t half = 0; half < 2u; ++half) {
        #pragma unroll
        for (uint32_t h = 0; h < 8u; ++h) {
            const uint32_t l = half * 8u + h;
            const float s  = kScale[l];
            const float sx = pt.x * s;
            const float sy = pt.y * s;

            const float fxf = floorf(sx);
            const float fyf = floorf(sy);
            const uint32_t fx = (uint32_t)(int32_t)fxf;
            const uint32_t fy = (uint32_t)(int32_t)fyf;
            const uint32_t cx = (uint32_t)(int32_t)ceilf(sx);
            const uint32_t cy = (uint32_t)(int32_t)ceilf(sy);
            const float ox = sx - fxf;
            const float oy = sy - fyf;

            const uint32_t base = l * TABLE_SIZE;
            const uint32_t hyc  = cy * HASH_PRIME;
            const uint32_t hyf  = fy * HASH_PRIME;
            // v0=(cx,cy) v1=(cx,fy) v2=(fx,cy) v3=(fx,fy)
            const uint32_t h0 = ((cx ^ hyc) & (TABLE_SIZE - 1u)) + base;
            const uint32_t h1 = ((cx ^ hyf) & (TABLE_SIZE - 1u)) + base;
            const uint32_t h2 = ((fx ^ hyc) & (TABLE_SIZE - 1u)) + base;
            const uint32_t h3 = ((fx ^ hyf) & (TABLE_SIZE - 1u)) + base;

            const float2 f0 = __ldg(&table[h0]);
            const float2 f1 = __ldg(&table[h1]);
            const float2 f2 = __ldg(&table[h2]);
            const float2 f3 = __ldg(&table[h3]);

            const float omx = 1.0f - ox;
            const float omy = 1.0f - oy;
            float2 e;
            e.x = (f0.x * ox + f3.x * omx) * oy + (f1.x * ox + f2.x * omx) * omy;
            e.y = (f0.y * ox + f3.y * omx) * oy + (f1.y * ox + f2.y * omx) * omy;

            srow[lane * ROW_F2 + h] = e;      // STS.64, 2-way max
        }
        __syncwarp();

        // transpose out: pass covers points {pc*8, .., pc*8+7}
        #pragma unroll
        for (uint32_t pass = 0; pass < 8u; ++pass) {
            const uint32_t q = pc * 8u + pass;               // warp point
            const float2 v = srow[q * ROW_F2 + pp];          // LDS.64, 2-way max
            const uint32_t oq = __shfl_sync(0xffffffffu, og, (int)q);
            out[(size_t)oq * 16u + half * 8u + pp] = v;      // STG.64, 4 rows/instr
        }
        __syncwarp();
    }
}

extern "C" void kernel_launch(void* const* d_in, const int* in_sizes, int n_in,
                              void* d_out, int out_size)
{
    const float2* x     = (const float2*)d_in[0];   // (N_POINTS, 2) float32
    const float2* table = (const float2*)d_in[1];   // (TABLE_SIZE*16, 2) float32
    float2* out = (float2*)d_out;                   // (N_POINTS, 32) float32

    uint32_t* inv;
    cudaGetSymbolAddress((void**)&inv, g_inv);

    hist_kernel     <<<N_POINTS / 512, 256>>>(x);
    scanA_kernel    <<<256, 256>>>();
    scanB_add_kernel<<<256, 256>>>();
    scatter_kernel  <<<N_POINTS / 1024, 256>>>(x);
    hash_encode_kernel<<<N_POINTS / M_BLOCK, M_BLOCK>>>(inv, x, table, out);
}

// round 14
// speedup vs baseline: 1.0529x; 1.0327x over previous
#include <cuda_runtime.h>
#include <cstdint>

#define TABLE_SIZE 524288u          // 2^19 -> modulo is a mask
#define NUM_LEVELS 16
#define N_POINTS (1u << 20)
#define HASH_PRIME 2654435761u

#define BINS_PER_AXIS 256u
#define NBINS (BINS_PER_AXIS * BINS_PER_AXIS)   // 65536 spatial bins

// -------- allocation-free scratch (device globals, zero-init at load) --------
__device__ uint32_t g_hist[NBINS];       // zero outside a launch chain:
                                         // hist fills it, scanA reads+rezeroes.
__device__ uint32_t g_cursor[NBINS];     // after scanB_add: global bin offset
__device__ uint32_t g_rowsum[BINS_PER_AXIS];
__device__ uint32_t g_pbr[N_POINTS];     // packed (bin<<16) | within-bin rank
__device__ uint32_t g_inv[N_POINTS];     // inverse permutation: sorted pos -> p

// scalings: floor(16 * (2^0.4)^l) in fp32, matching the reference exactly.
__constant__ float kScale[NUM_LEVELS] = {
    16.0f, 21.0f, 27.0f, 36.0f, 48.0f, 64.0f, 84.0f, 111.0f,
    147.0f, 194.0f, 256.0f, 337.0f, 445.0f, 588.0f, 776.0f, 1024.0f
};

__device__ __forceinline__ uint32_t bin_key(float xv, float yv)
{
    uint32_t kx = (uint32_t)(xv * 256.0f);
    uint32_t ky = (uint32_t)(yv * 256.0f);
    kx = kx > 255u ? 255u : kx;
    ky = ky > 255u ? 255u : ky;
    return (ky << 8) | kx;               // row-major
}

// ---------------- sort pipeline ----------------
// histogram + packed (bin, rank) per point
__global__ void hist_kernel(const float2* __restrict__ x)
{
    const uint32_t p = blockIdx.x * 256u + threadIdx.x;
    const float2 xp = __ldg(&x[p]);
    const uint32_t bin = bin_key(xp.x, xp.y);
    const uint32_t rk = atomicAdd(&g_hist[bin], 1u);
    g_pbr[p] = (bin << 16) | rk;         // rank << 65536 for uniform points
}

// scanA: 256 blocks; block b scans bins [b*256, b*256+256) -> local exclusive.
// Also re-zeroes g_hist so the next graph replay starts clean.
__global__ void scanA_kernel()
{
    __shared__ uint32_t s[256];
    const uint32_t t = threadIdx.x;
    const uint32_t i = blockIdx.x * 256u + t;
    const uint32_t v = g_hist[i];
    g_hist[i] = 0u;                             // restore for next replay
    s[t] = v;
    __syncthreads();
    #pragma unroll
    for (uint32_t off = 1u; off < 256u; off <<= 1) {
        uint32_t u = (t >= off) ? s[t - off] : 0u;
        __syncthreads();
        s[t] += u;
        __syncthreads();
    }
    g_cursor[i] = s[t] - v;                     // exclusive within row
    if (t == 255u) g_rowsum[blockIdx.x] = s[t]; // row total
}

// scanB_add: 256 blocks; each redundantly scans the 256 row sums and folds
// its row's offset into g_cursor -> cursor becomes a global bin offset.
__global__ void scanB_add_kernel()
{
    __shared__ uint32_t s[256];
    const uint32_t t = threadIdx.x;
    const uint32_t v = g_rowsum[t];
    s[t] = v;
    __syncthreads();
    #pragma unroll
    for (uint32_t off = 1u; off < 256u; off <<= 1) {
        uint32_t u = (t >= off) ? s[t - off] : 0u;
        __syncthreads();
        s[t] += u;
        __syncthreads();
    }
    const uint32_t rowoff = s[blockIdx.x] - g_rowsum[blockIdx.x];
    g_cursor[blockIdx.x * 256u + t] += rowoff;
}

// scatter: ATOMIC-FREE. One coalesced 4B load -> one gather -> one store.
__global__ void scatter_kernel()
{
    const uint32_t p = blockIdx.x * 256u + threadIdx.x;
    const uint32_t pbr = g_pbr[p];               // coalesced
    const uint32_t pos = __ldg(&g_cursor[pbr >> 16]) + (pbr & 0xFFFFu);
    g_inv[pos] = p;                              // scattered 4B store
}

// ---------------- main encode kernel ----------------
// lane = sorted point; warp = 32 spatially-adjacent points; loop over levels.
// All 16 levels buffered in smem (stride 17 float2 -> 2-way bank floor on
// both STS.64 and LDS.64), then 8 STG.128 per warp write 4 FULL 128B output
// rows each: 32 store wavefronts/warp (the line minimum).
#define M_BLOCK 256
#define ROW_F2 17                    // float2 stride per point (16 data + 1 pad)

__global__ __launch_bounds__(M_BLOCK)
void hash_encode_kernel(const uint32_t* __restrict__ inv,
                        const float2* __restrict__ x,
                        const float2* __restrict__ table,
                        float4* __restrict__ out)
{
    __shared__ float2 s_buf[M_BLOCK / 32][32 * ROW_F2];

    const uint32_t tid  = threadIdx.x;
    const uint32_t lane = tid & 31u;
    float2* const srow  = s_buf[tid >> 5];

    const uint32_t pos = blockIdx.x * M_BLOCK + tid;  // sorted position
    const uint32_t og  = __ldg(&inv[pos]);            // coalesced 4B
    const float2   pt  = __ldg(&x[og]);               // one divergent gather

    #pragma unroll
    for (uint32_t l = 0; l < NUM_LEVELS; ++l) {
        const float s  = kScale[l];
        const float sx = pt.x * s;
        const float sy = pt.y * s;

        const float fxf = floorf(sx);
        const float fyf = floorf(sy);
        const uint32_t fx = (uint32_t)(int32_t)fxf;
        const uint32_t fy = (uint32_t)(int32_t)fyf;
        const uint32_t cx = (uint32_t)(int32_t)ceilf(sx);
        const uint32_t cy = (uint32_t)(int32_t)ceilf(sy);
        const float ox = sx - fxf;
        const float oy = sy - fyf;

        const uint32_t base = l * TABLE_SIZE;
        const uint32_t hyc  = cy * HASH_PRIME;
        const uint32_t hyf  = fy * HASH_PRIME;
        // v0=(cx,cy) v1=(cx,fy) v2=(fx,cy) v3=(fx,fy)
        const uint32_t h0 = ((cx ^ hyc) & (TABLE_SIZE - 1u)) + base;
        const uint32_t h1 = ((cx ^ hyf) & (TABLE_SIZE - 1u)) + base;
        const uint32_t h2 = ((fx ^ hyc) & (TABLE_SIZE - 1u)) + base;
        const uint32_t h3 = ((fx ^ hyf) & (TABLE_SIZE - 1u)) + base;

        const float2 f0 = __ldg(&table[h0]);
        const float2 f1 = __ldg(&table[h1]);
        const float2 f2 = __ldg(&table[h2]);
        const float2 f3 = __ldg(&table[h3]);

        const float omx = 1.0f - ox;
        const float omy = 1.0f - oy;
        float2 e;
        e.x = (f0.x * ox + f3.x * omx) * oy + (f1.x * ox + f2.x * omx) * omy;
        e.y = (f0.y * ox + f3.y * omx) * oy + (f1.y * ox + f2.y * omx) * omy;

        srow[lane * ROW_F2 + l] = e;     // STS.64, bank-pair (lane+l)%16: 2-way
    }
    __syncwarp();

    // 8 STG.128: instr i covers rows q = i*4..i*4+3, pieces c = 0..7.
    // LDS.64 pairs at (17q + 2c), bank-pair (q+2c)%16: exactly 2-way.
    const uint32_t qr = lane >> 3;       // row-within-group 0..3
    const uint32_t c  = lane & 7u;       // float4 piece 0..7
    #pragma unroll
    for (uint32_t i = 0; i < 8u; ++i) {
        const uint32_t q = i * 4u + qr;                  // warp point
        const float2 a = srow[q * ROW_F2 + 2u * c];
        const float2 b = srow[q * ROW_F2 + 2u * c + 1u];
        const uint32_t oq = __shfl_sync(0xffffffffu, og, (int)q);
        out[(size_t)oq * 8u + c] = make_float4(a.x, a.y, b.x, b.y);
    }
}

extern "C" void kernel_launch(void* const* d_in, const int* in_sizes, int n_in,
                              void* d_out, int out_size)
{
    const float2* x     = (const float2*)d_in[0];   // (N_POINTS, 2) float32
    const float2* table = (const float2*)d_in[1];   // (TABLE_SIZE*16, 2) float32
    float4* out = (float4*)d_out;                   // (N_POINTS, 32) float32

    uint32_t* inv;
    cudaGetSymbolAddress((void**)&inv, g_inv);

    hist_kernel     <<<N_POINTS / 256, 256>>>(x);
    scanA_kernel    <<<256, 256>>>();
    scanB_add_kernel<<<256, 256>>>();
    scatter_kernel  <<<N_POINTS / 256, 256>>>();
    hash_encode_kernel<<<N_POINTS / M_BLOCK, M_BLOCK>>>(inv, x, table, out);
}

// round 15
// speedup vs baseline: 1.0734x; 1.0194x over previous
#include <cuda_runtime.h>
#include <cstdint>

#define TABLE_SIZE 524288u          // 2^19 -> modulo is a mask
#define NUM_LEVELS 16
#define N_POINTS (1u << 20)
#define HASH_PRIME 2654435761u

#define BINS_PER_AXIS 256u
#define NBINS (BINS_PER_AXIS * BINS_PER_AXIS)   // 65536 spatial bins
#define SS_BLOCKS 256u              // scan+scatter grid (co-resident, safe to spin)
#define PTS_PER_SS_BLOCK (N_POINTS / SS_BLOCKS) // 4096

// -------- allocation-free scratch (device globals, zero-init at load) --------
__device__ uint32_t g_hist[NBINS];       // zero outside a launch chain:
                                         // hist fills it, scan reads+rezeroes.
__device__ uint32_t g_cursor[NBINS];     // exclusive within row after phase 1
__device__ uint32_t g_rowsum[BINS_PER_AXIS];
__device__ uint32_t g_pbr[N_POINTS];     // packed (bin<<16) | within-bin rank
__device__ uint32_t g_inv[N_POINTS];     // inverse permutation: sorted pos -> p

// software grid barrier state (phase is monotonic across graph replays;
// count self-resets each barrier -> deterministic on every replay)
__device__ uint32_t g_sync_count;
__device__ volatile uint32_t g_sync_phase;

// scalings: floor(16 * (2^0.4)^l) in fp32, matching the reference exactly.
__constant__ float kScale[NUM_LEVELS] = {
    16.0f, 21.0f, 27.0f, 36.0f, 48.0f, 64.0f, 84.0f, 111.0f,
    147.0f, 194.0f, 256.0f, 337.0f, 445.0f, 588.0f, 776.0f, 1024.0f
};

__device__ __forceinline__ uint32_t bin_key(float xv, float yv)
{
    uint32_t kx = (uint32_t)(xv * 256.0f);
    uint32_t ky = (uint32_t)(yv * 256.0f);
    kx = kx > 255u ? 255u : kx;
    ky = ky > 255u ? 255u : ky;
    return (ky << 8) | kx;               // row-major
}

// ---------------- kernel 1: histogram + packed (bin, rank) ----------------
__global__ void hist_kernel(const float2* __restrict__ x)
{
    const uint32_t p = blockIdx.x * 256u + threadIdx.x;
    const float2 xp = __ldg(&x[p]);
    const uint32_t bin = bin_key(xp.x, xp.y);
    const uint32_t rk = atomicAdd(&g_hist[bin], 1u);
    g_pbr[p] = (bin << 16) | rk;         // rank << 65536 for uniform points
}

// ---------- kernel 2: fused scan (A+B) + scatter, one grid barrier ----------
// 256 blocks x 256 threads: guaranteed co-resident (capacity ~1184 blocks),
// so the spin barrier cannot deadlock.
__global__ __launch_bounds__(256)
void scan_scatter_kernel()
{
    __shared__ uint32_t s[256];
    __shared__ uint32_t sro[256];
    const uint32_t t = threadIdx.x;
    const uint32_t b = blockIdx.x;

    // ---- phase 1: scan own hist row -> row-exclusive cursor; rezero hist ----
    {
        const uint32_t i = b * 256u + t;
        const uint32_t v = g_hist[i];
        g_hist[i] = 0u;                         // restore for next replay
        s[t] = v;
        __syncthreads();
        #pragma unroll
        for (uint32_t off = 1u; off < 256u; off <<= 1) {
            uint32_t u = (t >= off) ? s[t - off] : 0u;
            __syncthreads();
            s[t] += u;
            __syncthreads();
        }
        g_cursor[i] = s[t] - v;                 // exclusive within row
        if (t == 255u) g_rowsum[b] = s[t];      // row total
    }

    // ---- grid barrier (sense-reversing, replay-safe) ----
    __threadfence();
    __syncthreads();
    if (t == 0u) {
        const uint32_t ph = g_sync_phase;       // read sense BEFORE arriving
        const uint32_t prev = atomicAdd(&g_sync_count, 1u);
        if (prev == SS_BLOCKS - 1u) {           // last block to arrive
            g_sync_count = 0u;                  // safe: everyone has arrived
            __threadfence();
            g_sync_phase = ph + 1u;             // release
        } else {
            while (g_sync_phase == ph) __nanosleep(100);
        }
    }
    __syncthreads();
    __threadfence();

    // ---- phase 2a: every block redundantly scans the 256 row sums ----
    {
        const uint32_t v = g_rowsum[t];
        s[t] = v;
        __syncthreads();
        #pragma unroll
        for (uint32_t off = 1u; off < 256u; off <<= 1) {
            uint32_t u = (t >= off) ? s[t - off] : 0u;
            __syncthreads();
            s[t] += u;
            __syncthreads();
        }
        sro[t] = s[t] - v;                      // row offsets
        __syncthreads();
    }

    // ---- phase 2b: scatter 16 points/thread (MLP-16 independent chains) ----
    const uint32_t base = b * PTS_PER_SS_BLOCK + t;
    #pragma unroll
    for (uint32_t k = 0; k < 16u; ++k) {
        const uint32_t p = base + k * 256u;
        const uint32_t pbr = g_pbr[p];           // coalesced
        const uint32_t bin = pbr >> 16;
        const uint32_t pos = __ldg(&g_cursor[bin]) + sro[bin >> 8]
                             + (pbr & 0xFFFFu);
        g_inv[pos] = p;                          // scattered 4B store
    }
}

// ---------------- kernel 3: encode ----------------
// lane = sorted point; warp = 32 spatially-adjacent points; loop over levels.
// All 16 levels buffered in smem (stride 17 float2 -> 2-way bank floor on
// both STS.64 and LDS.64), then 8 STG.128 per warp write 4 FULL 128B output
// rows each: 32 store wavefronts/warp (the line minimum).
#define M_BLOCK 256
#define ROW_F2 17                    // float2 stride per point (16 data + 1 pad)

__global__ __launch_bounds__(M_BLOCK)
void hash_encode_kernel(const uint32_t* __restrict__ inv,
                        const float2* __restrict__ x,
                        const float2* __restrict__ table,
                        float4* __restrict__ out)
{
    __shared__ float2 s_buf[M_BLOCK / 32][32 * ROW_F2];

    const uint32_t tid  = threadIdx.x;
    const uint32_t lane = tid & 31u;
    float2* const srow  = s_buf[tid >> 5];

    const uint32_t pos = blockIdx.x * M_BLOCK + tid;  // sorted position
    const uint32_t og  = __ldg(&inv[pos]);            // coalesced 4B
    const float2   pt  = __ldg(&x[og]);               // one divergent gather

    #pragma unroll
    for (uint32_t l = 0; l < NUM_LEVELS; ++l) {
        const float s  = kScale[l];
        const float sx = pt.x * s;
        const float sy = pt.y * s;

        const float fxf = floorf(sx);
        const float fyf = floorf(sy);
        const uint32_t fx = (uint32_t)(int32_t)fxf;
        const uint32_t fy = (uint32_t)(int32_t)fyf;
        const uint32_t cx = (uint32_t)(int32_t)ceilf(sx);
        const uint32_t cy = (uint32_t)(int32_t)ceilf(sy);
        const float ox = sx - fxf;
        const float oy = sy - fyf;

        const uint32_t base = l * TABLE_SIZE;
        const uint32_t hyc  = cy * HASH_PRIME;
        const uint32_t hyf  = fy * HASH_PRIME;
        // v0=(cx,cy) v1=(cx,fy) v2=(fx,cy) v3=(fx,fy)
        const uint32_t h0 = ((cx ^ hyc) & (TABLE_SIZE - 1u)) + base;
        const uint32_t h1 = ((cx ^ hyf) & (TABLE_SIZE - 1u)) + base;
        const uint32_t h2 = ((fx ^ hyc) & (TABLE_SIZE - 1u)) + base;
        const uint32_t h3 = ((fx ^ hyf) & (TABLE_SIZE - 1u)) + base;

        const float2 f0 = __ldg(&table[h0]);
        const float2 f1 = __ldg(&table[h1]);
        const float2 f2 = __ldg(&table[h2]);
        const float2 f3 = __ldg(&table[h3]);

        const float omx = 1.0f - ox;
        const float omy = 1.0f - oy;
        float2 e;
        e.x = (f0.x * ox + f3.x * omx) * oy + (f1.x * ox + f2.x * omx) * omy;
        e.y = (f0.y * ox + f3.y * omx) * oy + (f1.y * ox + f2.y * omx) * omy;

        srow[lane * ROW_F2 + l] = e;     // STS.64, bank-pair (lane+l)%16: 2-way
    }
    __syncwarp();

    // 8 STG.128: instr i covers rows q = i*4..i*4+3, pieces c = 0..7.
    // LDS.64 pairs at (17q + 2c), bank-pair (q+2c)%16: exactly 2-way.
    const uint32_t qr = lane >> 3;       // row-within-group 0..3
    const uint32_t c  = lane & 7u;       // float4 piece 0..7
    #pragma unroll
    for (uint32_t i = 0; i < 8u; ++i) {
        const uint32_t q = i * 4u + qr;                  // warp point
        const float2 a = srow[q * ROW_F2 + 2u * c];
        const float2 b = srow[q * ROW_F2 + 2u * c + 1u];
        const uint32_t oq = __shfl_sync(0xffffffffu, og, (int)q);
        out[(size_t)oq * 8u + c] = make_float4(a.x, a.y, b.x, b.y);
    }
}

extern "C" void kernel_launch(void* const* d_in, const int* in_sizes, int n_in,
                              void* d_out, int out_size)
{
    const float2* x     = (const float2*)d_in[0];   // (N_POINTS, 2) float32
    const float2* table = (const float2*)d_in[1];   // (TABLE_SIZE*16, 2) float32
    float4* out = (float4*)d_out;                   // (N_POINTS, 32) float32

    uint32_t* inv;
    cudaGetSymbolAddress((void**)&inv, g_inv);

    hist_kernel        <<<N_POINTS / 256, 256>>>(x);
    scan_scatter_kernel<<<SS_BLOCKS, 256>>>();
    hash_encode_kernel <<<N_POINTS / M_BLOCK, M_BLOCK>>>(inv, x, table, out);
}